// round 1
// baseline (speedup 1.0000x reference)
#include <cuda_runtime.h>

// Problem constants (fixed by the dataset)
#define BB   64
#define NN   2048
#define EE   32768
#define DD   256
#define HH   256

#define SPLIT_E 8      // blocks per batch for edge passes (E/SPLIT_E = 4096 edges/block)
#define SPLIT_M 16     // blocks per batch for embedding gather (N/SPLIT_M = 128 rows/block)

// Scratch (allocation-free: __device__ globals)
__device__ float g_w[BB * NN];     // w[b,m]
__device__ float g_u[BB * NN];     // u[b,m]
__device__ float g_c[BB];          // c[b]
__device__ float g_s0[BB * DD];    // S0[b,:]

// ---------------------------------------------------------------------------
// Kernel 0: zero scratch
// ---------------------------------------------------------------------------
__global__ void k_init() {
    int i = blockIdx.x * blockDim.x + threadIdx.x;
    int total = 2 * BB * NN + BB + BB * DD;
    if (i >= total) return;
    if (i < BB * NN)                 g_w[i] = 0.f;
    else if (i < 2 * BB * NN)        g_u[i - BB * NN] = 0.f;
    else if (i < 2 * BB * NN + BB)   g_c[i - 2 * BB * NN] = 0.f;
    else                             g_s0[i - 2 * BB * NN - BB] = 0.f;
}

// ---------------------------------------------------------------------------
// Kernel 1: w[b,m] = sum_{e: row<L, col==m} val ;  c[b] = sum_{e: row<L} val
// grid (B, SPLIT_E), 256 threads
// ---------------------------------------------------------------------------
__global__ void k_w(const int* __restrict__ adj_row,
                    const int* __restrict__ adj_col,
                    const float* __restrict__ adj_val,
                    const int* __restrict__ curlen) {
    __shared__ float sw[NN];
    __shared__ float sc;
    int b = blockIdx.x;
    int tid = threadIdx.x;
    for (int i = tid; i < NN; i += blockDim.x) sw[i] = 0.f;
    if (tid == 0) sc = 0.f;
    __syncthreads();

    int L = curlen ? *curlen : 512;
    const int CHUNK = EE / SPLIT_E;
    int e0 = blockIdx.y * CHUNK;
    size_t base = (size_t)b * EE;
    const int*   row = adj_row + base;
    const int*   col = adj_col + base;
    const float* val = adj_val + base;

    float cpart = 0.f;
    for (int e = e0 + tid; e < e0 + CHUNK; e += blockDim.x) {
        int r = row[e];
        if (r < L) {
            float v = val[e];
            atomicAdd(&sw[col[e]], v);
            cpart += v;
        }
    }
    // warp reduce cpart, then one shared atomic per warp
    #pragma unroll
    for (int off = 16; off > 0; off >>= 1)
        cpart += __shfl_down_sync(0xFFFFFFFFu, cpart, off);
    if ((tid & 31) == 0) atomicAdd(&sc, cpart);
    __syncthreads();

    float* gw = g_w + (size_t)b * NN;
    for (int i = tid; i < NN; i += blockDim.x) {
        float v = sw[i];
        if (v != 0.f) atomicAdd(&gw[i], v);
    }
    if (tid == 0) atomicAdd(&g_c[b], sc);
}

// ---------------------------------------------------------------------------
// Kernel 2: u[b,m] = sum_{e: col==m} val * w[b, row]
// grid (B, SPLIT_E), 256 threads
// ---------------------------------------------------------------------------
__global__ void k_u(const int* __restrict__ adj_row,
                    const int* __restrict__ adj_col,
                    const float* __restrict__ adj_val) {
    __shared__ float sw[NN];
    __shared__ float su[NN];
    int b = blockIdx.x;
    int tid = threadIdx.x;
    const float* gw = g_w + (size_t)b * NN;
    for (int i = tid; i < NN; i += blockDim.x) { sw[i] = gw[i]; su[i] = 0.f; }
    __syncthreads();

    const int CHUNK = EE / SPLIT_E;
    int e0 = blockIdx.y * CHUNK;
    size_t base = (size_t)b * EE;
    const int*   row = adj_row + base;
    const int*   col = adj_col + base;
    const float* val = adj_val + base;

    for (int e = e0 + tid; e < e0 + CHUNK; e += blockDim.x) {
        float wv = sw[row[e]];
        if (wv != 0.f) atomicAdd(&su[col[e]], val[e] * wv);
    }
    __syncthreads();

    float* gu = g_u + (size_t)b * NN;
    for (int i = tid; i < NN; i += blockDim.x) {
        float v = su[i];
        if (v != 0.f) atomicAdd(&gu[i], v);
    }
}

// ---------------------------------------------------------------------------
// Kernel 3: S0[b,:] = sum_m u[b,m] * emb[neighbors[b,m], :]
// grid (B, SPLIT_M), 256 threads: thread d accumulates component d
// ---------------------------------------------------------------------------
__global__ void k_s0(const int* __restrict__ neighbors,
                     const float* __restrict__ emb) {
    const int MPB = NN / SPLIT_M;  // 128 rows per block
    __shared__ float su[MPB];
    __shared__ int   snb[MPB];
    int b = blockIdx.x;
    int tid = threadIdx.x;
    int m0 = blockIdx.y * MPB;

    if (tid < MPB) {
        su[tid]  = g_u[(size_t)b * NN + m0 + tid];
        snb[tid] = neighbors[(size_t)b * NN + m0 + tid];
    }
    __syncthreads();

    int d = tid;
    float a0 = 0.f, a1 = 0.f, a2 = 0.f, a3 = 0.f;
    #pragma unroll 4
    for (int i = 0; i < MPB; i += 4) {
        float u0 = su[i + 0], u1 = su[i + 1], u2 = su[i + 2], u3 = su[i + 3];
        if (u0 != 0.f) a0 += u0 * emb[(size_t)snb[i + 0] * DD + d];
        if (u1 != 0.f) a1 += u1 * emb[(size_t)snb[i + 1] * DD + d];
        if (u2 != 0.f) a2 += u2 * emb[(size_t)snb[i + 2] * DD + d];
        if (u3 != 0.f) a3 += u3 * emb[(size_t)snb[i + 3] * DD + d];
    }
    atomicAdd(&g_s0[(size_t)b * DD + d], (a0 + a1) + (a2 + a3));
}

// ---------------------------------------------------------------------------
// Kernel 4: S1 = c*b1 + S0@W1 ; pooled = S1@W2 / L + b2 ; out = relu(pooled@fc1_w + fc1_b)
// grid (B), 256 threads: thread h owns output column h of each matvec
// ---------------------------------------------------------------------------
__global__ void k_final(const float* __restrict__ W1, const float* __restrict__ b1,
                        const float* __restrict__ W2, const float* __restrict__ b2,
                        const float* __restrict__ fc1w, const float* __restrict__ fc1b,
                        const int* __restrict__ curlen,
                        float* __restrict__ out) {
    __shared__ float v0[DD];
    __shared__ float v1[HH];
    __shared__ float v2[HH];
    int b = blockIdx.x;
    int h = threadIdx.x;

    v0[h] = g_s0[(size_t)b * DD + h];
    __syncthreads();

    float acc = 0.f;
    #pragma unroll 8
    for (int d = 0; d < DD; d++) acc += v0[d] * W1[d * HH + h];
    float c = g_c[b];
    v1[h] = acc + c * b1[h];
    __syncthreads();

    acc = 0.f;
    #pragma unroll 8
    for (int d = 0; d < HH; d++) acc += v1[d] * W2[d * HH + h];
    int L = curlen ? *curlen : 512;
    v2[h] = acc * (1.f / (float)L) + b2[h];
    __syncthreads();

    acc = 0.f;
    #pragma unroll 8
    for (int d = 0; d < HH; d++) acc += v2[d] * fc1w[d * HH + h];
    float o = acc + fc1b[h];
    out[(size_t)b * HH + h] = o > 0.f ? o : 0.f;
}

// ---------------------------------------------------------------------------
extern "C" void kernel_launch(void* const* d_in, const int* in_sizes, int n_in,
                              void* d_out, int out_size) {
    const int*   neighbors = (const int*)  d_in[0];
    const int*   adj_row   = (const int*)  d_in[1];
    const int*   adj_col   = (const int*)  d_in[2];
    const float* adj_val   = (const float*)d_in[3];
    const float* emb       = (const float*)d_in[4];
    const float* W1        = (const float*)d_in[5];
    const float* b1        = (const float*)d_in[6];
    const float* W2        = (const float*)d_in[7];
    const float* b2        = (const float*)d_in[8];
    const float* fc1w      = (const float*)d_in[9];
    const float* fc1b      = (const float*)d_in[10];
    const int*   curlen    = (n_in >= 12) ? (const int*)d_in[11] : nullptr;
    float*       out       = (float*)d_out;

    int init_total = 2 * BB * NN + BB + BB * DD;
    k_init<<<(init_total + 255) / 256, 256>>>();
    k_w  <<<dim3(BB, SPLIT_E), 256>>>(adj_row, adj_col, adj_val, curlen);
    k_u  <<<dim3(BB, SPLIT_E), 256>>>(adj_row, adj_col, adj_val);
    k_s0 <<<dim3(BB, SPLIT_M), 256>>>(neighbors, emb);
    k_final<<<BB, 256>>>(W1, b1, W2, b2, fc1w, fc1b, curlen, out);
}

// round 2
// speedup vs baseline: 1.3501x; 1.3501x over previous
#include <cuda_runtime.h>

// Problem constants (fixed by the dataset)
#define BB   64
#define NN   2048
#define EE   32768
#define DD   256
#define HH   256

#define SPLIT_M 16                 // gather blocks per batch
#define MPB    (NN / SPLIT_M)      // 128 rows per gather block

// Scratch (allocation-free: __device__ globals). No init kernel needed:
// every element below is written with '=' before it is read.
__device__ float g_u[BB * NN];               // u[b,m]
__device__ float g_c[BB];                    // c[b]
__device__ float g_s0p[SPLIT_M * BB * DD];   // per-split S0 partials

// ---------------------------------------------------------------------------
// Kernel 1 (fused): per-batch block computes
//   w[m] = sum_{e: row<L, col==m} val          (shared)
//   c    = sum_{e: row<L} val
//   u[m] = sum_{e} val * w[row_e]              -> g_u, g_c
// grid (B), 1024 threads. Both edge passes inside one block => __syncthreads
// replaces the old kernel boundary and the g_w global round-trip.
// ---------------------------------------------------------------------------
__global__ __launch_bounds__(1024) void k_wu(const int* __restrict__ adj_row,
                                             const int* __restrict__ adj_col,
                                             const float* __restrict__ adj_val,
                                             const int* __restrict__ curlen) {
    __shared__ float sw[NN];
    __shared__ float su[NN];
    __shared__ float sc;
    int b = blockIdx.x;
    int tid = threadIdx.x;

    for (int i = tid; i < NN; i += 1024) { sw[i] = 0.f; su[i] = 0.f; }
    if (tid == 0) sc = 0.f;
    __syncthreads();

    int L = curlen ? *curlen : 512;
    size_t base = (size_t)b * EE;
    const int4*   r4 = (const int4*)  (adj_row + base);
    const int4*   c4 = (const int4*)  (adj_col + base);
    const float4* v4 = (const float4*)(adj_val + base);
    const int NV = EE / 4;  // 8192

    // Pass 1: w scatter + c reduce
    float cpart = 0.f;
    for (int i = tid; i < NV; i += 1024) {
        int4 r = r4[i]; int4 c = c4[i]; float4 v = v4[i];
        if (r.x < L) { atomicAdd(&sw[c.x], v.x); cpart += v.x; }
        if (r.y < L) { atomicAdd(&sw[c.y], v.y); cpart += v.y; }
        if (r.z < L) { atomicAdd(&sw[c.z], v.z); cpart += v.z; }
        if (r.w < L) { atomicAdd(&sw[c.w], v.w); cpart += v.w; }
    }
    #pragma unroll
    for (int off = 16; off > 0; off >>= 1)
        cpart += __shfl_down_sync(0xFFFFFFFFu, cpart, off);
    if ((tid & 31) == 0) atomicAdd(&sc, cpart);
    __syncthreads();

    // Pass 2: u scatter (edge data re-read hits L2: 24 MB total working set)
    for (int i = tid; i < NV; i += 1024) {
        int4 r = r4[i]; int4 c = c4[i]; float4 v = v4[i];
        atomicAdd(&su[c.x], v.x * sw[r.x]);
        atomicAdd(&su[c.y], v.y * sw[r.y]);
        atomicAdd(&su[c.z], v.z * sw[r.z]);
        atomicAdd(&su[c.w], v.w * sw[r.w]);
    }
    __syncthreads();

    float* gu = g_u + (size_t)b * NN;
    for (int i = tid; i < NN; i += 1024) gu[i] = su[i];
    if (tid == 0) g_c[b] = sc;
}

// ---------------------------------------------------------------------------
// Kernel 2: S0 partials. Each block gathers MPB=128 embedding rows.
// Thread layout: dg = tid&63 owns float4 of dims [4dg..4dg+3]; rg = tid>>6
// strides over rows. Unconditional float4 gathers, unrolled x4 for MLP.
// grid (B, SPLIT_M), 256 threads.
// ---------------------------------------------------------------------------
__global__ __launch_bounds__(256) void k_s0(const int* __restrict__ neighbors,
                                            const float* __restrict__ emb) {
    __shared__ float  su[MPB];
    __shared__ int    snb[MPB];
    __shared__ float4 red[4][64];
    int b   = blockIdx.x;
    int tid = threadIdx.x;
    int m0  = blockIdx.y * MPB;

    if (tid < MPB) {
        su[tid]  = g_u[(size_t)b * NN + m0 + tid];
        snb[tid] = neighbors[(size_t)b * NN + m0 + tid];
    }
    __syncthreads();

    int dg = tid & 63;
    int rg = tid >> 6;

    float4 acc = make_float4(0.f, 0.f, 0.f, 0.f);
    #pragma unroll 4
    for (int i = rg; i < MPB; i += 4) {
        float u = su[i];
        const float4* row = (const float4*)(emb + (size_t)snb[i] * DD);
        float4 e = __ldg(&row[dg]);
        acc.x += u * e.x;
        acc.y += u * e.y;
        acc.z += u * e.z;
        acc.w += u * e.w;
    }
    red[rg][dg] = acc;
    __syncthreads();

    if (tid < 64) {
        float4 a = red[0][tid], b1 = red[1][tid], c = red[2][tid], d = red[3][tid];
        float4 s;
        s.x = (a.x + b1.x) + (c.x + d.x);
        s.y = (a.y + b1.y) + (c.y + d.y);
        s.z = (a.z + b1.z) + (c.z + d.z);
        s.w = (a.w + b1.w) + (c.w + d.w);
        float4* dst = (float4*)(g_s0p + ((size_t)blockIdx.y * BB + b) * DD);
        dst[tid] = s;
    }
}

// ---------------------------------------------------------------------------
// Kernel 3: reduce S0 partials, then the fused linear chain + ReLU.
// grid (B), 256 threads (thread h owns output column h).
// ---------------------------------------------------------------------------
__global__ __launch_bounds__(256) void k_final(
        const float* __restrict__ W1, const float* __restrict__ b1,
        const float* __restrict__ W2, const float* __restrict__ b2,
        const float* __restrict__ fc1w, const float* __restrict__ fc1b,
        const int* __restrict__ curlen,
        float* __restrict__ out) {
    __shared__ float v0[DD];
    __shared__ float v1[HH];
    __shared__ float v2[HH];
    int b = blockIdx.x;
    int h = threadIdx.x;

    float s0 = 0.f;
    #pragma unroll
    for (int sm = 0; sm < SPLIT_M; sm++)
        s0 += g_s0p[((size_t)sm * BB + b) * DD + h];
    v0[h] = s0;
    __syncthreads();

    float acc = 0.f;
    #pragma unroll 8
    for (int d = 0; d < DD; d++) acc += v0[d] * W1[d * HH + h];
    float c = g_c[b];
    v1[h] = acc + c * b1[h];
    __syncthreads();

    acc = 0.f;
    #pragma unroll 8
    for (int d = 0; d < HH; d++) acc += v1[d] * W2[d * HH + h];
    int L = curlen ? *curlen : 512;
    v2[h] = acc * (1.f / (float)L) + b2[h];
    __syncthreads();

    acc = 0.f;
    #pragma unroll 8
    for (int d = 0; d < HH; d++) acc += v2[d] * fc1w[d * HH + h];
    float o = acc + fc1b[h];
    out[(size_t)b * HH + h] = o > 0.f ? o : 0.f;
}

// ---------------------------------------------------------------------------
extern "C" void kernel_launch(void* const* d_in, const int* in_sizes, int n_in,
                              void* d_out, int out_size) {
    const int*   neighbors = (const int*)  d_in[0];
    const int*   adj_row   = (const int*)  d_in[1];
    const int*   adj_col   = (const int*)  d_in[2];
    const float* adj_val   = (const float*)d_in[3];
    const float* emb       = (const float*)d_in[4];
    const float* W1        = (const float*)d_in[5];
    const float* b1        = (const float*)d_in[6];
    const float* W2        = (const float*)d_in[7];
    const float* b2        = (const float*)d_in[8];
    const float* fc1w      = (const float*)d_in[9];
    const float* fc1b      = (const float*)d_in[10];
    const int*   curlen    = (n_in >= 12) ? (const int*)d_in[11] : nullptr;
    float*       out       = (float*)d_out;

    k_wu   <<<BB, 1024>>>(adj_row, adj_col, adj_val, curlen);
    k_s0   <<<dim3(BB, SPLIT_M), 256>>>(neighbors, emb);
    k_final<<<BB, 256>>>(W1, b1, W2, b2, fc1w, fc1b, curlen, out);
}

// round 3
// speedup vs baseline: 1.3987x; 1.0360x over previous
#include <cuda_runtime.h>

// Problem constants (fixed by the dataset)
#define BB   64
#define NN   2048
#define EE   32768
#define DD   256
#define HH   256

#define SE      4                  // edge-pass blocks per batch
#define EPB     (EE / SE)          // 8192 edges per block
#define SPLIT_M 16                 // gather blocks per batch
#define MPB     (NN / SPLIT_M)     // 128 rows per gather block

// Scratch (__device__ globals, allocation-free). All partial buffers are
// written with plain stores before being read -> no init kernel needed.
__device__ float g_wp[SE * BB * NN];         // w partials per edge-split
__device__ float g_up[SE * BB * NN];         // u partials per edge-split
__device__ float g_cp[SE * BB];              // c partials per edge-split
__device__ float g_s0p[SPLIT_M * BB * DD];   // S0 partials per gather-split

// ---------------------------------------------------------------------------
// Kernel 1: w partials.  w[b,m] = sum_{e: row<L, col==m} val,  c = sum val.
// grid (BB, SE), 512 threads. Shared scatter, plain-store partials out.
// ---------------------------------------------------------------------------
__global__ __launch_bounds__(512) void k_w(const int* __restrict__ adj_row,
                                           const int* __restrict__ adj_col,
                                           const float* __restrict__ adj_val,
                                           const int* __restrict__ curlen) {
    __shared__ float sw[NN];
    __shared__ float sc;
    int b   = blockIdx.x;
    int se  = blockIdx.y;
    int tid = threadIdx.x;

    for (int i = tid; i < NN; i += 512) sw[i] = 0.f;
    if (tid == 0) sc = 0.f;
    __syncthreads();

    int L = curlen ? *curlen : 512;
    size_t base = (size_t)b * EE + (size_t)se * EPB;
    const int4*   r4 = (const int4*)  (adj_row + base);
    const int4*   c4 = (const int4*)  (adj_col + base);
    const float4* v4 = (const float4*)(adj_val + base);
    const int NV = EPB / 4;  // 2048 vec-groups

    float cpart = 0.f;
    for (int i = tid; i < NV; i += 512) {
        int4 r = r4[i]; int4 c = c4[i]; float4 v = v4[i];
        if (r.x < L) { atomicAdd(&sw[c.x], v.x); cpart += v.x; }
        if (r.y < L) { atomicAdd(&sw[c.y], v.y); cpart += v.y; }
        if (r.z < L) { atomicAdd(&sw[c.z], v.z); cpart += v.z; }
        if (r.w < L) { atomicAdd(&sw[c.w], v.w); cpart += v.w; }
    }
    #pragma unroll
    for (int off = 16; off > 0; off >>= 1)
        cpart += __shfl_down_sync(0xFFFFFFFFu, cpart, off);
    if ((tid & 31) == 0) atomicAdd(&sc, cpart);
    __syncthreads();

    float* dst = g_wp + ((size_t)se * BB + b) * NN;
    for (int i = tid; i < NN; i += 512) dst[i] = sw[i];
    if (tid == 0) g_cp[se * BB + b] = sc;
}

// ---------------------------------------------------------------------------
// Kernel 2: u partials.  u[b,m] = sum_{e: col==m} val * w[b,row].
// grid (BB, SE), 512 threads. Loads full w by summing SE partials (L2 hits).
// ---------------------------------------------------------------------------
__global__ __launch_bounds__(512) void k_u(const int* __restrict__ adj_row,
                                           const int* __restrict__ adj_col,
                                           const float* __restrict__ adj_val) {
    __shared__ float sw[NN];
    __shared__ float su[NN];
    int b   = blockIdx.x;
    int se  = blockIdx.y;
    int tid = threadIdx.x;

    for (int i = tid; i < NN; i += 512) {
        float w = 0.f;
        #pragma unroll
        for (int s = 0; s < SE; s++)
            w += g_wp[((size_t)s * BB + b) * NN + i];
        sw[i] = w;
        su[i] = 0.f;
    }
    __syncthreads();

    size_t base = (size_t)b * EE + (size_t)se * EPB;
    const int4*   r4 = (const int4*)  (adj_row + base);
    const int4*   c4 = (const int4*)  (adj_col + base);
    const float4* v4 = (const float4*)(adj_val + base);
    const int NV = EPB / 4;

    for (int i = tid; i < NV; i += 512) {
        int4 r = r4[i]; int4 c = c4[i]; float4 v = v4[i];
        atomicAdd(&su[c.x], v.x * sw[r.x]);
        atomicAdd(&su[c.y], v.y * sw[r.y]);
        atomicAdd(&su[c.z], v.z * sw[r.z]);
        atomicAdd(&su[c.w], v.w * sw[r.w]);
    }
    __syncthreads();

    float* dst = g_up + ((size_t)se * BB + b) * NN;
    for (int i = tid; i < NN; i += 512) dst[i] = su[i];
}

// ---------------------------------------------------------------------------
// Kernel 3: S0 partials. Each block gathers MPB=128 embedding rows.
// 512 threads: dg = tid&63 owns float4 lane, rg = tid>>6 (0..7) strides rows.
// 16 row iterations fully unrolled -> deep MLP. grid (BB, SPLIT_M).
// ---------------------------------------------------------------------------
__global__ __launch_bounds__(512) void k_s0(const int* __restrict__ neighbors,
                                            const float* __restrict__ emb) {
    __shared__ float  su[MPB];
    __shared__ int    snb[MPB];
    __shared__ float4 red[8][64];
    int b   = blockIdx.x;
    int tid = threadIdx.x;
    int m0  = blockIdx.y * MPB;

    if (tid < MPB) {
        float u = 0.f;
        #pragma unroll
        for (int s = 0; s < SE; s++)
            u += g_up[((size_t)s * BB + b) * NN + m0 + tid];
        su[tid]  = u;
        snb[tid] = neighbors[(size_t)b * NN + m0 + tid];
    }
    __syncthreads();

    int dg = tid & 63;
    int rg = tid >> 6;   // 0..7

    float4 acc = make_float4(0.f, 0.f, 0.f, 0.f);
    #pragma unroll
    for (int i = rg; i < MPB; i += 8) {
        float u = su[i];
        const float4* row = (const float4*)(emb + (size_t)snb[i] * DD);
        float4 e = __ldg(&row[dg]);
        acc.x += u * e.x;
        acc.y += u * e.y;
        acc.z += u * e.z;
        acc.w += u * e.w;
    }
    red[rg][dg] = acc;
    __syncthreads();

    if (tid < 64) {
        float4 s = make_float4(0.f, 0.f, 0.f, 0.f);
        #pragma unroll
        for (int r = 0; r < 8; r++) {
            float4 a = red[r][tid];
            s.x += a.x; s.y += a.y; s.z += a.z; s.w += a.w;
        }
        float4* dst = (float4*)(g_s0p + ((size_t)blockIdx.y * BB + b) * DD);
        dst[tid] = s;
    }
}

// ---------------------------------------------------------------------------
// Kernel 4: reduce S0/c partials, then fused linear chain + ReLU.
// grid (BB), 256 threads (thread h owns output column h).
// ---------------------------------------------------------------------------
__global__ __launch_bounds__(256) void k_final(
        const float* __restrict__ W1, const float* __restrict__ b1,
        const float* __restrict__ W2, const float* __restrict__ b2,
        const float* __restrict__ fc1w, const float* __restrict__ fc1b,
        const int* __restrict__ curlen,
        float* __restrict__ out) {
    __shared__ float v0[DD];
    __shared__ float v1[HH];
    __shared__ float v2[HH];
    int b = blockIdx.x;
    int h = threadIdx.x;

    float s0 = 0.f;
    #pragma unroll
    for (int sm = 0; sm < SPLIT_M; sm++)
        s0 += g_s0p[((size_t)sm * BB + b) * DD + h];
    v0[h] = s0;
    __syncthreads();

    float acc = 0.f;
    #pragma unroll 8
    for (int d = 0; d < DD; d++) acc += v0[d] * W1[d * HH + h];
    float c = 0.f;
    #pragma unroll
    for (int s = 0; s < SE; s++) c += g_cp[s * BB + b];
    v1[h] = acc + c * b1[h];
    __syncthreads();

    acc = 0.f;
    #pragma unroll 8
    for (int d = 0; d < HH; d++) acc += v1[d] * W2[d * HH + h];
    int L = curlen ? *curlen : 512;
    v2[h] = acc * (1.f / (float)L) + b2[h];
    __syncthreads();

    acc = 0.f;
    #pragma unroll 8
    for (int d = 0; d < HH; d++) acc += v2[d] * fc1w[d * HH + h];
    float o = acc + fc1b[h];
    out[(size_t)b * HH + h] = o > 0.f ? o : 0.f;
}

// ---------------------------------------------------------------------------
extern "C" void kernel_launch(void* const* d_in, const int* in_sizes, int n_in,
                              void* d_out, int out_size) {
    const int*   neighbors = (const int*)  d_in[0];
    const int*   adj_row   = (const int*)  d_in[1];
    const int*   adj_col   = (const int*)  d_in[2];
    const float* adj_val   = (const float*)d_in[3];
    const float* emb       = (const float*)d_in[4];
    const float* W1        = (const float*)d_in[5];
    const float* b1        = (const float*)d_in[6];
    const float* W2        = (const float*)d_in[7];
    const float* b2        = (const float*)d_in[8];
    const float* fc1w      = (const float*)d_in[9];
    const float* fc1b      = (const float*)d_in[10];
    const int*   curlen    = (n_in >= 12) ? (const int*)d_in[11] : nullptr;
    float*       out       = (float*)d_out;

    k_w    <<<dim3(BB, SE), 512>>>(adj_row, adj_col, adj_val, curlen);
    k_u    <<<dim3(BB, SE), 512>>>(adj_row, adj_col, adj_val);
    k_s0   <<<dim3(BB, SPLIT_M), 512>>>(neighbors, emb);
    k_final<<<BB, 256>>>(W1, b1, W2, b2, fc1w, fc1b, curlen, out);
}

// round 4
// speedup vs baseline: 2.3440x; 1.6759x over previous
#include <cuda_runtime.h>

// Problem constants (fixed by the dataset)
#define BB   64
#define NN   2048
#define EE   32768
#define DD   256
#define HH   256

#define SE      4                  // edge-pass blocks per batch
#define EPB     (EE / SE)          // 8192 edges per block
#define SPLIT_M 16                 // gather blocks per batch
#define MPB     (NN / SPLIT_M)     // 128 rows per gather block

// Scratch (__device__ globals, allocation-free). All partial buffers are
// written with plain stores before being read -> no init kernel needed.
__device__ float g_wp[SE * BB * NN];         // w partials per edge-split
__device__ float g_up[SE * BB * NN];         // u partials per edge-split
__device__ float g_cp[SE * BB];              // c partials per edge-split
__device__ float g_s0p[SPLIT_M * BB * DD];   // S0 partials per gather-split
__device__ float g_v1[BB * HH];              // S1 = S0@W1 + c*b1
__device__ float g_v2[BB * HH];              // pooled = S1@W2/L + b2

// ---------------------------------------------------------------------------
// Kernel 1: w partials.  w[b,m] = sum_{e: row<L, col==m} val,  c = sum val.
// grid (BB, SE), 512 threads.
// ---------------------------------------------------------------------------
__global__ __launch_bounds__(512) void k_w(const int* __restrict__ adj_row,
                                           const int* __restrict__ adj_col,
                                           const float* __restrict__ adj_val,
                                           const int* __restrict__ curlen) {
    __shared__ float sw[NN];
    __shared__ float sc;
    int b   = blockIdx.x;
    int se  = blockIdx.y;
    int tid = threadIdx.x;

    for (int i = tid; i < NN; i += 512) sw[i] = 0.f;
    if (tid == 0) sc = 0.f;
    __syncthreads();

    int L = curlen ? *curlen : 512;
    size_t base = (size_t)b * EE + (size_t)se * EPB;
    const int4*   r4 = (const int4*)  (adj_row + base);
    const int4*   c4 = (const int4*)  (adj_col + base);
    const float4* v4 = (const float4*)(adj_val + base);
    const int NV = EPB / 4;  // 2048 vec-groups

    float cpart = 0.f;
    for (int i = tid; i < NV; i += 512) {
        int4 r = r4[i]; int4 c = c4[i]; float4 v = v4[i];
        if (r.x < L) { atomicAdd(&sw[c.x], v.x); cpart += v.x; }
        if (r.y < L) { atomicAdd(&sw[c.y], v.y); cpart += v.y; }
        if (r.z < L) { atomicAdd(&sw[c.z], v.z); cpart += v.z; }
        if (r.w < L) { atomicAdd(&sw[c.w], v.w); cpart += v.w; }
    }
    #pragma unroll
    for (int off = 16; off > 0; off >>= 1)
        cpart += __shfl_down_sync(0xFFFFFFFFu, cpart, off);
    if ((tid & 31) == 0) atomicAdd(&sc, cpart);
    __syncthreads();

    float* dst = g_wp + ((size_t)se * BB + b) * NN;
    for (int i = tid; i < NN; i += 512) dst[i] = sw[i];
    if (tid == 0) g_cp[se * BB + b] = sc;
}

// ---------------------------------------------------------------------------
// Kernel 2: u partials.  u[b,m] = sum_{e: col==m} val * w[b,row].
// grid (BB, SE), 512 threads.
// ---------------------------------------------------------------------------
__global__ __launch_bounds__(512) void k_u(const int* __restrict__ adj_row,
                                           const int* __restrict__ adj_col,
                                           const float* __restrict__ adj_val) {
    __shared__ float sw[NN];
    __shared__ float su[NN];
    int b   = blockIdx.x;
    int se  = blockIdx.y;
    int tid = threadIdx.x;

    for (int i = tid; i < NN; i += 512) {
        float w = 0.f;
        #pragma unroll
        for (int s = 0; s < SE; s++)
            w += g_wp[((size_t)s * BB + b) * NN + i];
        sw[i] = w;
        su[i] = 0.f;
    }
    __syncthreads();

    size_t base = (size_t)b * EE + (size_t)se * EPB;
    const int4*   r4 = (const int4*)  (adj_row + base);
    const int4*   c4 = (const int4*)  (adj_col + base);
    const float4* v4 = (const float4*)(adj_val + base);
    const int NV = EPB / 4;

    for (int i = tid; i < NV; i += 512) {
        int4 r = r4[i]; int4 c = c4[i]; float4 v = v4[i];
        atomicAdd(&su[c.x], v.x * sw[r.x]);
        atomicAdd(&su[c.y], v.y * sw[r.y]);
        atomicAdd(&su[c.z], v.z * sw[r.z]);
        atomicAdd(&su[c.w], v.w * sw[r.w]);
    }
    __syncthreads();

    float* dst = g_up + ((size_t)se * BB + b) * NN;
    for (int i = tid; i < NN; i += 512) dst[i] = su[i];
}

// ---------------------------------------------------------------------------
// Kernel 3: S0 partials. Each block gathers MPB=128 embedding rows.
// 512 threads: dg = tid&63 owns a float4 lane, rg = tid>>6 strides rows.
// grid (BB, SPLIT_M).
// ---------------------------------------------------------------------------
__global__ __launch_bounds__(512) void k_s0(const int* __restrict__ neighbors,
                                            const float* __restrict__ emb) {
    __shared__ float  su[MPB];
    __shared__ int    snb[MPB];
    __shared__ float4 red[8][64];
    int b   = blockIdx.x;
    int tid = threadIdx.x;
    int m0  = blockIdx.y * MPB;

    if (tid < MPB) {
        float u = 0.f;
        #pragma unroll
        for (int s = 0; s < SE; s++)
            u += g_up[((size_t)s * BB + b) * NN + m0 + tid];
        su[tid]  = u;
        snb[tid] = neighbors[(size_t)b * NN + m0 + tid];
    }
    __syncthreads();

    int dg = tid & 63;
    int rg = tid >> 6;   // 0..7

    float4 acc = make_float4(0.f, 0.f, 0.f, 0.f);
    #pragma unroll
    for (int i = rg; i < MPB; i += 8) {
        float u = su[i];
        const float4* row = (const float4*)(emb + (size_t)snb[i] * DD);
        float4 e = __ldg(&row[dg]);
        acc.x += u * e.x;
        acc.y += u * e.y;
        acc.z += u * e.z;
        acc.w += u * e.w;
    }
    red[rg][dg] = acc;
    __syncthreads();

    if (tid < 64) {
        float4 s = make_float4(0.f, 0.f, 0.f, 0.f);
        #pragma unroll
        for (int r = 0; r < 8; r++) {
            float4 a = red[r][tid];
            s.x += a.x; s.y += a.y; s.z += a.z; s.w += a.w;
        }
        float4* dst = (float4*)(g_s0p + ((size_t)blockIdx.y * BB + b) * DD);
        dst[tid] = s;
    }
}

// ---------------------------------------------------------------------------
// Matvec kernels: grid (BB), block 1024. 4 threads cooperate per output
// column h (q = tid>>8 handles 64 d's each, fully unrolled -> deep MLP),
// shared reduce, fused per-kernel epilogue. Per-thread serial L2 loads: 64.
// ---------------------------------------------------------------------------

// mv1: v1[b,h] = sum_d S0[b,d]*W1[d,h] + c[b]*b1[h]
__global__ __launch_bounds__(1024) void k_mv1(const float* __restrict__ W1,
                                              const float* __restrict__ b1) {
    __shared__ float sx[DD];
    __shared__ float red[4][HH];
    __shared__ float sc;
    int b   = blockIdx.x;
    int tid = threadIdx.x;
    int h   = tid & 255;
    int q   = tid >> 8;

    if (tid < DD) {
        float s0 = 0.f;
        #pragma unroll
        for (int sm = 0; sm < SPLIT_M; sm++)
            s0 += g_s0p[((size_t)sm * BB + b) * DD + tid];
        sx[tid] = s0;
    }
    if (tid == DD) {
        float c = 0.f;
        #pragma unroll
        for (int s = 0; s < SE; s++) c += g_cp[s * BB + b];
        sc = c;
    }
    __syncthreads();

    float acc = 0.f;
    int d0 = q * 64;
    #pragma unroll
    for (int d = 0; d < 64; d++)
        acc += sx[d0 + d] * W1[(size_t)(d0 + d) * HH + h];
    red[q][h] = acc;
    __syncthreads();

    if (tid < HH) {
        float s = (red[0][tid] + red[1][tid]) + (red[2][tid] + red[3][tid]);
        g_v1[(size_t)b * HH + tid] = s + sc * b1[tid];
    }
}

// mv2: v2[b,h] = (sum_d v1[b,d]*W2[d,h]) / L + b2[h]
__global__ __launch_bounds__(1024) void k_mv2(const float* __restrict__ W2,
                                              const float* __restrict__ b2,
                                              const int* __restrict__ curlen) {
    __shared__ float sx[HH];
    __shared__ float red[4][HH];
    int b   = blockIdx.x;
    int tid = threadIdx.x;
    int h   = tid & 255;
    int q   = tid >> 8;

    if (tid < HH) sx[tid] = g_v1[(size_t)b * HH + tid];
    __syncthreads();

    float acc = 0.f;
    int d0 = q * 64;
    #pragma unroll
    for (int d = 0; d < 64; d++)
        acc += sx[d0 + d] * W2[(size_t)(d0 + d) * HH + h];
    red[q][h] = acc;
    __syncthreads();

    if (tid < HH) {
        int L = curlen ? *curlen : 512;
        float s = (red[0][tid] + red[1][tid]) + (red[2][tid] + red[3][tid]);
        g_v2[(size_t)b * HH + tid] = s * (1.f / (float)L) + b2[tid];
    }
}

// mv3: out[b,h] = relu(sum_d v2[b,d]*fc1w[d,h] + fc1b[h])
__global__ __launch_bounds__(1024) void k_mv3(const float* __restrict__ fc1w,
                                              const float* __restrict__ fc1b,
                                              float* __restrict__ out) {
    __shared__ float sx[HH];
    __shared__ float red[4][HH];
    int b   = blockIdx.x;
    int tid = threadIdx.x;
    int h   = tid & 255;
    int q   = tid >> 8;

    if (tid < HH) sx[tid] = g_v2[(size_t)b * HH + tid];
    __syncthreads();

    float acc = 0.f;
    int d0 = q * 64;
    #pragma unroll
    for (int d = 0; d < 64; d++)
        acc += sx[d0 + d] * fc1w[(size_t)(d0 + d) * HH + h];
    red[q][h] = acc;
    __syncthreads();

    if (tid < HH) {
        float s = (red[0][tid] + red[1][tid]) + (red[2][tid] + red[3][tid]);
        float o = s + fc1b[tid];
        out[(size_t)b * HH + tid] = o > 0.f ? o : 0.f;
    }
}

// ---------------------------------------------------------------------------
extern "C" void kernel_launch(void* const* d_in, const int* in_sizes, int n_in,
                              void* d_out, int out_size) {
    const int*   neighbors = (const int*)  d_in[0];
    const int*   adj_row   = (const int*)  d_in[1];
    const int*   adj_col   = (const int*)  d_in[2];
    const float* adj_val   = (const float*)d_in[3];
    const float* emb       = (const float*)d_in[4];
    const float* W1        = (const float*)d_in[5];
    const float* b1        = (const float*)d_in[6];
    const float* W2        = (const float*)d_in[7];
    const float* b2        = (const float*)d_in[8];
    const float* fc1w      = (const float*)d_in[9];
    const float* fc1b      = (const float*)d_in[10];
    const int*   curlen    = (n_in >= 12) ? (const int*)d_in[11] : nullptr;
    float*       out       = (float*)d_out;

    k_w  <<<dim3(BB, SE), 512>>>(adj_row, adj_col, adj_val, curlen);
    k_u  <<<dim3(BB, SE), 512>>>(adj_row, adj_col, adj_val);
    k_s0 <<<dim3(BB, SPLIT_M), 512>>>(neighbors, emb);
    k_mv1<<<BB, 1024>>>(W1, b1);
    k_mv2<<<BB, 1024>>>(W2, b2, curlen);
    k_mv3<<<BB, 1024>>>(fc1w, fc1b, out);
}

// round 5
// speedup vs baseline: 2.6715x; 1.1397x over previous
#include <cuda_runtime.h>

// Problem constants (fixed by the dataset)
#define BB   64
#define NN   2048
#define EE   32768
#define DD   256
#define HH   256

#define SE      4                  // edge-pass blocks per batch
#define EPB     (EE / SE)          // 8192 edges per block
#define SPLIT_M 16                 // gather blocks per batch
#define MPB     (NN / SPLIT_M)     // 128 rows per gather block

// Scratch (__device__ globals, allocation-free). All partial buffers are
// written with plain stores before being read -> no init kernel needed.
__device__ float g_wp[SE * BB * NN];         // w partials per edge-split
__device__ float g_up[SE * BB * NN];         // u partials per edge-split
__device__ float g_cp[SE * BB];              // c partials per edge-split
__device__ float g_s0p[SPLIT_M * BB * DD];   // S0 partials per gather-split

// ---------------------------------------------------------------------------
// Kernel 1: w partials.  w[b,m] = sum_{e: row<L, col==m} val,  c = sum val.
// grid (BB, SE), 512 threads.
// ---------------------------------------------------------------------------
__global__ __launch_bounds__(512) void k_w(const int* __restrict__ adj_row,
                                           const int* __restrict__ adj_col,
                                           const float* __restrict__ adj_val,
                                           const int* __restrict__ curlen) {
    __shared__ float sw[NN];
    __shared__ float sc;
    int b   = blockIdx.x;
    int se  = blockIdx.y;
    int tid = threadIdx.x;

    for (int i = tid; i < NN; i += 512) sw[i] = 0.f;
    if (tid == 0) sc = 0.f;
    __syncthreads();

    int L = curlen ? *curlen : 512;
    size_t base = (size_t)b * EE + (size_t)se * EPB;
    const int4*   r4 = (const int4*)  (adj_row + base);
    const int4*   c4 = (const int4*)  (adj_col + base);
    const float4* v4 = (const float4*)(adj_val + base);
    const int NV = EPB / 4;  // 2048 vec-groups

    float cpart = 0.f;
    for (int i = tid; i < NV; i += 512) {
        int4 r = r4[i]; int4 c = c4[i]; float4 v = v4[i];
        if (r.x < L) { atomicAdd(&sw[c.x], v.x); cpart += v.x; }
        if (r.y < L) { atomicAdd(&sw[c.y], v.y); cpart += v.y; }
        if (r.z < L) { atomicAdd(&sw[c.z], v.z); cpart += v.z; }
        if (r.w < L) { atomicAdd(&sw[c.w], v.w); cpart += v.w; }
    }
    #pragma unroll
    for (int off = 16; off > 0; off >>= 1)
        cpart += __shfl_down_sync(0xFFFFFFFFu, cpart, off);
    if ((tid & 31) == 0) atomicAdd(&sc, cpart);
    __syncthreads();

    float* dst = g_wp + ((size_t)se * BB + b) * NN;
    for (int i = tid; i < NN; i += 512) dst[i] = sw[i];
    if (tid == 0) g_cp[se * BB + b] = sc;
}

// ---------------------------------------------------------------------------
// Kernel 2: u partials.  u[b,m] = sum_{e: col==m} val * w[b,row].
// grid (BB, SE), 512 threads.
// ---------------------------------------------------------------------------
__global__ __launch_bounds__(512) void k_u(const int* __restrict__ adj_row,
                                           const int* __restrict__ adj_col,
                                           const float* __restrict__ adj_val) {
    __shared__ float sw[NN];
    __shared__ float su[NN];
    int b   = blockIdx.x;
    int se  = blockIdx.y;
    int tid = threadIdx.x;

    for (int i = tid; i < NN; i += 512) {
        float w = 0.f;
        #pragma unroll
        for (int s = 0; s < SE; s++)
            w += g_wp[((size_t)s * BB + b) * NN + i];
        sw[i] = w;
        su[i] = 0.f;
    }
    __syncthreads();

    size_t base = (size_t)b * EE + (size_t)se * EPB;
    const int4*   r4 = (const int4*)  (adj_row + base);
    const int4*   c4 = (const int4*)  (adj_col + base);
    const float4* v4 = (const float4*)(adj_val + base);
    const int NV = EPB / 4;

    for (int i = tid; i < NV; i += 512) {
        int4 r = r4[i]; int4 c = c4[i]; float4 v = v4[i];
        atomicAdd(&su[c.x], v.x * sw[r.x]);
        atomicAdd(&su[c.y], v.y * sw[r.y]);
        atomicAdd(&su[c.z], v.z * sw[r.z]);
        atomicAdd(&su[c.w], v.w * sw[r.w]);
    }
    __syncthreads();

    float* dst = g_up + ((size_t)se * BB + b) * NN;
    for (int i = tid; i < NN; i += 512) dst[i] = su[i];
}

// ---------------------------------------------------------------------------
// Kernel 3: S0 partials. Each block gathers MPB=128 embedding rows.
// 512 threads: dg = tid&63 owns a float4 lane, rg = tid>>6 strides rows.
// grid (BB, SPLIT_M).
// ---------------------------------------------------------------------------
__global__ __launch_bounds__(512) void k_s0(const int* __restrict__ neighbors,
                                            const float* __restrict__ emb) {
    __shared__ float  su[MPB];
    __shared__ int    snb[MPB];
    __shared__ float4 red[8][64];
    int b   = blockIdx.x;
    int tid = threadIdx.x;
    int m0  = blockIdx.y * MPB;

    if (tid < MPB) {
        float u = 0.f;
        #pragma unroll
        for (int s = 0; s < SE; s++)
            u += g_up[((size_t)s * BB + b) * NN + m0 + tid];
        su[tid]  = u;
        snb[tid] = neighbors[(size_t)b * NN + m0 + tid];
    }
    __syncthreads();

    int dg = tid & 63;
    int rg = tid >> 6;   // 0..7

    float4 acc = make_float4(0.f, 0.f, 0.f, 0.f);
    #pragma unroll
    for (int i = rg; i < MPB; i += 8) {
        float u = su[i];
        const float4* row = (const float4*)(emb + (size_t)snb[i] * DD);
        float4 e = __ldg(&row[dg]);
        acc.x += u * e.x;
        acc.y += u * e.y;
        acc.z += u * e.z;
        acc.w += u * e.w;
    }
    red[rg][dg] = acc;
    __syncthreads();

    if (tid < 64) {
        float4 s = make_float4(0.f, 0.f, 0.f, 0.f);
        #pragma unroll
        for (int r = 0; r < 8; r++) {
            float4 a = red[r][tid];
            s.x += a.x; s.y += a.y; s.z += a.z; s.w += a.w;
        }
        float4* dst = (float4*)(g_s0p + ((size_t)blockIdx.y * BB + b) * DD);
        dst[tid] = s;
    }
}

// ---------------------------------------------------------------------------
// Kernel 4: fused 3-matvec chain, one block per batch, 1024 threads.
// Layout: hq = tid&63 owns float4 of h's [4hq..4hq+3]; q = tid>>6 (0..15)
// owns d-chunk [16q..16q+15]. Per stage: 16 coalesced float4 loads/thread
// (fully unrolled -> deep MLP), shared reduce over q, epilogue by tid<64.
// ---------------------------------------------------------------------------
__global__ __launch_bounds__(1024) void k_chain(
        const float* __restrict__ W1, const float* __restrict__ b1,
        const float* __restrict__ W2, const float* __restrict__ b2,
        const float* __restrict__ fc1w, const float* __restrict__ fc1b,
        const int* __restrict__ curlen,
        float* __restrict__ out) {
    __shared__ float  sx[HH];
    __shared__ float  sy[HH];
    __shared__ float4 red[16][64];
    __shared__ float  sc;
    int b   = blockIdx.x;
    int tid = threadIdx.x;
    int hq  = tid & 63;
    int q   = tid >> 6;

    if (tid < HH) {
        float s0 = 0.f;
        #pragma unroll
        for (int sm = 0; sm < SPLIT_M; sm++)
            s0 += g_s0p[((size_t)sm * BB + b) * DD + tid];
        sx[tid] = s0;
    } else if (tid == HH) {
        float c = 0.f;
        #pragma unroll
        for (int s = 0; s < SE; s++) c += g_cp[s * BB + b];
        sc = c;
    }
    __syncthreads();

    // ---- stage 1: sy = sx @ W1 + sc*b1 ----
    {
        const float4* W4 = (const float4*)W1;
        float4 acc = make_float4(0.f, 0.f, 0.f, 0.f);
        #pragma unroll
        for (int j = 0; j < 16; j++) {
            int d = q * 16 + j;
            float xv = sx[d];
            float4 wv = __ldg(&W4[(size_t)d * 64 + hq]);
            acc.x += xv * wv.x; acc.y += xv * wv.y;
            acc.z += xv * wv.z; acc.w += xv * wv.w;
        }
        red[q][hq] = acc;
        __syncthreads();
        if (tid < 64) {
            float4 s = make_float4(0.f, 0.f, 0.f, 0.f);
            #pragma unroll
            for (int r = 0; r < 16; r++) {
                float4 a = red[r][tid];
                s.x += a.x; s.y += a.y; s.z += a.z; s.w += a.w;
            }
            float4 bb = ((const float4*)b1)[tid];
            float  c  = sc;
            s.x += c * bb.x; s.y += c * bb.y; s.z += c * bb.z; s.w += c * bb.w;
            ((float4*)sy)[tid] = s;
        }
        __syncthreads();
    }

    // ---- stage 2: sx = (sy @ W2) / L + b2 ----
    {
        const float4* W4 = (const float4*)W2;
        float4 acc = make_float4(0.f, 0.f, 0.f, 0.f);
        #pragma unroll
        for (int j = 0; j < 16; j++) {
            int d = q * 16 + j;
            float xv = sy[d];
            float4 wv = __ldg(&W4[(size_t)d * 64 + hq]);
            acc.x += xv * wv.x; acc.y += xv * wv.y;
            acc.z += xv * wv.z; acc.w += xv * wv.w;
        }
        red[q][hq] = acc;
        __syncthreads();
        if (tid < 64) {
            float4 s = make_float4(0.f, 0.f, 0.f, 0.f);
            #pragma unroll
            for (int r = 0; r < 16; r++) {
                float4 a = red[r][tid];
                s.x += a.x; s.y += a.y; s.z += a.z; s.w += a.w;
            }
            int L = curlen ? *curlen : 512;
            float invL = 1.f / (float)L;
            float4 bb = ((const float4*)b2)[tid];
            s.x = s.x * invL + bb.x; s.y = s.y * invL + bb.y;
            s.z = s.z * invL + bb.z; s.w = s.w * invL + bb.w;
            ((float4*)sx)[tid] = s;
        }
        __syncthreads();
    }

    // ---- stage 3: out = relu(sx @ fc1w + fc1b) ----
    {
        const float4* W4 = (const float4*)fc1w;
        float4 acc = make_float4(0.f, 0.f, 0.f, 0.f);
        #pragma unroll
        for (int j = 0; j < 16; j++) {
            int d = q * 16 + j;
            float xv = sx[d];
            float4 wv = __ldg(&W4[(size_t)d * 64 + hq]);
            acc.x += xv * wv.x; acc.y += xv * wv.y;
            acc.z += xv * wv.z; acc.w += xv * wv.w;
        }
        red[q][hq] = acc;
        __syncthreads();
        if (tid < 64) {
            float4 s = make_float4(0.f, 0.f, 0.f, 0.f);
            #pragma unroll
            for (int r = 0; r < 16; r++) {
                float4 a = red[r][tid];
                s.x += a.x; s.y += a.y; s.z += a.z; s.w += a.w;
            }
            float4 bb = ((const float4*)fc1b)[tid];
            s.x += bb.x; s.y += bb.y; s.z += bb.z; s.w += bb.w;
            s.x = s.x > 0.f ? s.x : 0.f;
            s.y = s.y > 0.f ? s.y : 0.f;
            s.z = s.z > 0.f ? s.z : 0.f;
            s.w = s.w > 0.f ? s.w : 0.f;
            ((float4*)(out + (size_t)b * HH))[tid] = s;
        }
    }
}

// ---------------------------------------------------------------------------
extern "C" void kernel_launch(void* const* d_in, const int* in_sizes, int n_in,
                              void* d_out, int out_size) {
    const int*   neighbors = (const int*)  d_in[0];
    const int*   adj_row   = (const int*)  d_in[1];
    const int*   adj_col   = (const int*)  d_in[2];
    const float* adj_val   = (const float*)d_in[3];
    const float* emb       = (const float*)d_in[4];
    const float* W1        = (const float*)d_in[5];
    const float* b1        = (const float*)d_in[6];
    const float* W2        = (const float*)d_in[7];
    const float* b2        = (const float*)d_in[8];
    const float* fc1w      = (const float*)d_in[9];
    const float* fc1b      = (const float*)d_in[10];
    const int*   curlen    = (n_in >= 12) ? (const int*)d_in[11] : nullptr;
    float*       out       = (float*)d_out;

    k_w    <<<dim3(BB, SE), 512>>>(adj_row, adj_col, adj_val, curlen);
    k_u    <<<dim3(BB, SE), 512>>>(adj_row, adj_col, adj_val);
    k_s0   <<<dim3(BB, SPLIT_M), 512>>>(neighbors, emb);
    k_chain<<<BB, 1024>>>(W1, b1, W2, b2, fc1w, fc1b, curlen, out);
}